// round 2
// baseline (speedup 1.0000x reference)
#include <cuda_runtime.h>

// CrossCompressUnit: B=262144 rows, D=64.
// v_out = v * (e·w_vv) + e * (v·w_ev) + bias_v
// e_out = v * (e·w_ve) + e * (v·w_ee) + bias_e
// Pure HBM-streaming: 128 MB in, 128 MB out. Half-warp (16 lanes) per row,
// float4 accesses, butterfly-shuffle reductions. No smem, no barriers.

#define D 64
#define VEC 4            // float4
#define LANES_PER_ROW (D / VEC)   // 16

__global__ __launch_bounds__(256, 8)
void cross_compress_kernel(const float* __restrict__ v,
                           const float* __restrict__ e,
                           const float* __restrict__ w_vv,
                           const float* __restrict__ w_ev,
                           const float* __restrict__ w_ve,
                           const float* __restrict__ w_ee,
                           const float* __restrict__ bias_v,
                           const float* __restrict__ bias_e,
                           float* __restrict__ v_out,
                           float* __restrict__ e_out,
                           int n_rows)
{
    const int tid      = blockIdx.x * blockDim.x + threadIdx.x;
    const int row      = tid / LANES_PER_ROW;       // one row per 16 lanes
    const int l        = tid & (LANES_PER_ROW - 1); // 0..15 within row
    if (row >= n_rows) return;

    const long long base4 = (long long)row * LANES_PER_ROW + l; // float4 index

    const float4* v4p = (const float4*)v;
    const float4* e4p = (const float4*)e;

    float4 v4 = __ldg(&v4p[base4]);
    float4 e4 = __ldg(&e4p[base4]);

    // weight/bias slices for this lane (L1-resident)
    float4 wvv = __ldg(&((const float4*)w_vv)[l]);
    float4 wev = __ldg(&((const float4*)w_ev)[l]);
    float4 wve = __ldg(&((const float4*)w_ve)[l]);
    float4 wee = __ldg(&((const float4*)w_ee)[l]);
    float4 bv  = __ldg(&((const float4*)bias_v)[l]);
    float4 be  = __ldg(&((const float4*)bias_e)[l]);

    // 4 partial dot products
    float a = e4.x*wvv.x + e4.y*wvv.y + e4.z*wvv.z + e4.w*wvv.w; // e·w_vv
    float b = v4.x*wev.x + v4.y*wev.y + v4.z*wev.z + v4.w*wev.w; // v·w_ev
    float c = e4.x*wve.x + e4.y*wve.y + e4.z*wve.z + e4.w*wve.w; // e·w_ve
    float d = v4.x*wee.x + v4.y*wee.y + v4.z*wee.z + v4.w*wee.w; // v·w_ee

    // reduce across the 16-lane group (xor masks < 16 keep it in-group)
    #pragma unroll
    for (int m = 8; m >= 1; m >>= 1) {
        a += __shfl_xor_sync(0xffffffffu, a, m);
        b += __shfl_xor_sync(0xffffffffu, b, m);
        c += __shfl_xor_sync(0xffffffffu, c, m);
        d += __shfl_xor_sync(0xffffffffu, d, m);
    }

    float4 vo, eo;
    vo.x = fmaf(v4.x, a, fmaf(e4.x, b, bv.x));
    vo.y = fmaf(v4.y, a, fmaf(e4.y, b, bv.y));
    vo.z = fmaf(v4.z, a, fmaf(e4.z, b, bv.z));
    vo.w = fmaf(v4.w, a, fmaf(e4.w, b, bv.w));

    eo.x = fmaf(v4.x, c, fmaf(e4.x, d, be.x));
    eo.y = fmaf(v4.y, c, fmaf(e4.y, d, be.y));
    eo.z = fmaf(v4.z, c, fmaf(e4.z, d, be.z));
    eo.w = fmaf(v4.w, c, fmaf(e4.w, d, be.w));

    ((float4*)v_out)[base4] = vo;
    ((float4*)e_out)[base4] = eo;
}

extern "C" void kernel_launch(void* const* d_in, const int* in_sizes, int n_in,
                              void* d_out, int out_size)
{
    const float* v      = (const float*)d_in[0];
    const float* e      = (const float*)d_in[1];
    const float* w_vv   = (const float*)d_in[2];
    const float* w_ev   = (const float*)d_in[3];
    const float* w_ve   = (const float*)d_in[4];
    const float* w_ee   = (const float*)d_in[5];
    const float* bias_v = (const float*)d_in[6];
    const float* bias_e = (const float*)d_in[7];

    const int n_rows = in_sizes[0] / D;       // B = 262144

    float* out   = (float*)d_out;
    float* v_out = out;                        // first half: v_out [B, D]
    float* e_out = out + (long long)n_rows * D; // second half: e_out [B, D]

    const int threads = 256;
    const long long total_threads = (long long)n_rows * LANES_PER_ROW;
    const int blocks = (int)((total_threads + threads - 1) / threads);

    cross_compress_kernel<<<blocks, threads>>>(v, e, w_vv, w_ev, w_ve, w_ee,
                                               bias_v, bias_e, v_out, e_out,
                                               n_rows);
}